// round 7
// baseline (speedup 1.0000x reference)
#include <cuda_runtime.h>
#include <cuda_bf16.h>
#include <cstdint>
#include <cstddef>

// Problem dims (fixed by the reference)
#define BB   64
#define TT   4096
#define DE   512
#define DA   256

// ---------------- scratch (device globals; no allocation in kernel_launch) ----------------
__device__ __nv_bfloat16 g_henc_bf[(size_t)BB * TT * DE];   // 256 MB
__device__ __nv_bfloat16 g_wk_bf[DA * DE];                  // 256 KB
__device__ float         g_qpk[BB * DA];                    // q + Wq_b + Wk_b
__device__ float         g_scores2[2][(size_t)BB * TT];     // per-N-half partial scores

// ---------------- PTX helpers (compute_103-safe: no tcgen05/TMEM) ----------------
__device__ __forceinline__ uint32_t smem_u32(const void* p) {
    uint32_t a;
    asm("{ .reg .u64 t; cvta.to.shared.u64 t, %1; cvt.u32.u64 %0, t; }" : "=r"(a) : "l"(p));
    return a;
}
__device__ __forceinline__ void cp_async16(uint32_t dst, const void* src) {
    asm volatile("cp.async.cg.shared.global [%0], [%1], 16;" :: "r"(dst), "l"(src) : "memory");
}
__device__ __forceinline__ void cp_commit() {
    asm volatile("cp.async.commit_group;" ::: "memory");
}
template <int N>
__device__ __forceinline__ void cp_wait() {
    asm volatile("cp.async.wait_group %0;" :: "n"(N) : "memory");
}
__device__ __forceinline__ void ldmatrix_x4(uint32_t* r, uint32_t addr) {
    asm volatile("ldmatrix.sync.aligned.m8n8.x4.shared.b16 {%0,%1,%2,%3}, [%4];"
                 : "=r"(r[0]), "=r"(r[1]), "=r"(r[2]), "=r"(r[3]) : "r"(addr));
}
__device__ __forceinline__ void ldmatrix_x2(uint32_t* r, uint32_t addr) {
    asm volatile("ldmatrix.sync.aligned.m8n8.x2.shared.b16 {%0,%1}, [%2];"
                 : "=r"(r[0]), "=r"(r[1]) : "r"(addr));
}
__device__ __forceinline__ void mma16816(float* c, const uint32_t* a, const uint32_t* b) {
    asm volatile(
        "mma.sync.aligned.m16n8k16.row.col.f32.bf16.bf16.f32 "
        "{%0,%1,%2,%3}, {%4,%5,%6,%7}, {%8,%9}, {%0,%1,%2,%3};"
        : "+f"(c[0]), "+f"(c[1]), "+f"(c[2]), "+f"(c[3])
        : "r"(a[0]), "r"(a[1]), "r"(a[2]), "r"(a[3]), "r"(b[0]), "r"(b[1]));
}
__device__ __forceinline__ float tanh_approx(float x) {
    float y;
    asm("tanh.approx.f32 %0, %1;" : "=f"(y) : "f"(x));
    return y;
}

// SW128 swizzle (Swizzle<3,4,3>) on tile-local byte offsets, rows = 128B
#define SWZ(o) ((o) ^ (((o) >> 3) & 0x70))

// ---------------- kernel 1: f32 -> bf16 convert ----------------
__global__ void convert_kernel(const float* __restrict__ src, __nv_bfloat16* __restrict__ dst, long n4) {
    long i = (long)blockIdx.x * blockDim.x + threadIdx.x;
    if (i >= n4) return;
    float4 v = reinterpret_cast<const float4*>(src)[i];
    __nv_bfloat162 lo = __floats2bfloat162_rn(v.x, v.y);
    __nv_bfloat162 hi = __floats2bfloat162_rn(v.z, v.w);
    uint2 o;
    o.x = *reinterpret_cast<uint32_t*>(&lo);
    o.y = *reinterpret_cast<uint32_t*>(&hi);
    reinterpret_cast<uint2*>(dst)[i] = o;
}

// ---------------- kernel 2: qpk[b,a] = h_dec[b]·Wq[a] + Wq_b[a] + Wk_b[a] ----------------
__global__ void qpk_kernel(const float* __restrict__ hdec, const float* __restrict__ Wq,
                           const float* __restrict__ Wqb, const float* __restrict__ Wkb,
                           float* __restrict__ qpk) {
    int b = blockIdx.x;
    int a = threadIdx.x;  // 256
    __shared__ float h[DE];
    for (int e = threadIdx.x; e < DE; e += 256) h[e] = hdec[b * DE + e];
    __syncthreads();
    const float* w = Wq + (size_t)a * DE;
    float acc = 0.f;
#pragma unroll 8
    for (int e = 0; e < DE; e++) acc = fmaf(h[e], w[e], acc);
    qpk[b * DA + a] = acc + Wqb[a] + Wkb[a];
}

// ---------------- kernel 3: mma.sync GEMM + fused score epilogue ----------------
// CTA tile: M=128 (rows of one b), N=128 (one half of DA), K=512 in 8 chunks of 64.
// 8 warps = 2(M) x 4(N); warp tile 64x32. Double-buffered cp.async.
// SMEM layout (dynamic):
#define SM_PART   0                 // float s_part[4][128] = 2048 B
#define SM_V      2048              // float sv[128]
#define SM_Q      2560              // float sq[128]
#define SM_A(st)  (4096 + (st) * 16384)       // A stage: 128 rows x 128 B
#define SM_B(st)  (36864 + (st) * 16384)      // B stage: 128 rows x 128 B
#define GEMM_SMEM 69632

__global__ void __launch_bounds__(256, 2) gemm_score_kernel(
    const __nv_bfloat16* __restrict__ A,    // [B*T, 512] bf16
    const __nv_bfloat16* __restrict__ Bm,   // [256, 512] bf16 (Wk)
    const float* __restrict__ qpk,
    const float* __restrict__ v_w,
    float* __restrict__ sc2) {              // [2][B*T]
    extern __shared__ char smem[];
    uint32_t sb = smem_u32(smem);
    int tid = threadIdx.x;
    int wid = tid >> 5, lane = tid & 31;
    int wm = wid >> 2, wn = wid & 3;
    int g = lane >> 2, tig = lane & 3;

    // grid: bx = (b*32 + mt)*2 + nh  -> adjacent CTAs share the A tile (L2 reuse)
    int nh = blockIdx.x & 1;
    int mt = (blockIdx.x >> 1) & 31;
    int b  = blockIdx.x >> 6;
    int t0 = mt << 7;
    size_t m0 = ((size_t)b * 32 + mt) * 128;

    // stage v and qpk slice for this N-half
    if (tid < 128) {
        ((float*)(smem + SM_V))[tid] = v_w[nh * 128 + tid];
        ((float*)(smem + SM_Q))[tid] = qpk[b * DA + nh * 128 + tid];
    }

    const __nv_bfloat16* Bh = Bm + (size_t)(nh * 128) * DE;

    // ---- async loaders: one k-chunk = A 128x64 + B 128x64 bf16 (16 KB each) ----
    auto issue = [&](int kc, int st) {
        uint32_t aS = sb + SM_A(st), bS = sb + SM_B(st);
        const __nv_bfloat16* ab = A + m0 * DE + kc * 64;
        const __nv_bfloat16* bb = Bh + kc * 64;
#pragma unroll
        for (int i = 0; i < 4; i++) {
            int c = tid + i * 256;
            int row = c >> 3, cc = c & 7;
            cp_async16(aS + SWZ(row * 128 + cc * 16), ab + (size_t)row * DE + cc * 8);
        }
#pragma unroll
        for (int i = 0; i < 4; i++) {
            int c = tid + i * 256;
            int row = c >> 3, cc = c & 7;
            cp_async16(bS + SWZ(row * 128 + cc * 16), bb + (size_t)row * DE + cc * 8);
        }
        cp_commit();
    };

    float acc[4][4][4];
#pragma unroll
    for (int mi = 0; mi < 4; mi++)
#pragma unroll
        for (int ni = 0; ni < 4; ni++)
#pragma unroll
            for (int e = 0; e < 4; e++) acc[mi][ni][e] = 0.f;

    // ldmatrix per-lane row/col-block selectors
    int arow = wm * 64 + (lane & 15);     // + mi*16
    int acb  = lane >> 4;                 // 0/1 -> +16B (k 8..15)
    int brow = wn * 32 + (lane & 7);      // + ni*8
    int bkb  = (lane >> 3) & 1;           // 0/1 -> +16B

    issue(0, 0);

#pragma unroll 1
    for (int kc = 0; kc < 8; kc++) {
        if (kc < 7) {
            issue(kc + 1, (kc + 1) & 1);
            cp_wait<1>();
        } else {
            cp_wait<0>();
        }
        __syncthreads();

        uint32_t aS = sb + SM_A(kc & 1), bS = sb + SM_B(kc & 1);
#pragma unroll
        for (int ks = 0; ks < 4; ks++) {
            uint32_t af[4][4], bf_[4][2];
#pragma unroll
            for (int mi = 0; mi < 4; mi++)
                ldmatrix_x4(af[mi], aS + SWZ((arow + mi * 16) * 128 + ks * 32 + acb * 16));
#pragma unroll
            for (int ni = 0; ni < 4; ni++)
                ldmatrix_x2(bf_[ni], bS + SWZ((brow + ni * 8) * 128 + ks * 32 + bkb * 16));
#pragma unroll
            for (int mi = 0; mi < 4; mi++)
#pragma unroll
                for (int ni = 0; ni < 4; ni++)
                    mma16816(acc[mi][ni], af[mi], bf_[ni]);
        }
        __syncthreads();
    }

    // ---- epilogue: partial score = sum over this half's a of v*tanh(qpk + k) ----
    const float* sv = (const float*)(smem + SM_V);
    const float* sq = (const float*)(smem + SM_Q);
    float* s_part = (float*)(smem + SM_PART);

#pragma unroll
    for (int mi = 0; mi < 4; mi++) {
        float plo = 0.f, phi = 0.f;
#pragma unroll
        for (int ni = 0; ni < 4; ni++) {
            int n = wn * 32 + ni * 8 + tig * 2;
            float v0 = sv[n], v1 = sv[n + 1], q0 = sq[n], q1 = sq[n + 1];
            plo = fmaf(v0, tanh_approx(q0 + acc[mi][ni][0]), plo);
            plo = fmaf(v1, tanh_approx(q1 + acc[mi][ni][1]), plo);
            phi = fmaf(v0, tanh_approx(q0 + acc[mi][ni][2]), phi);
            phi = fmaf(v1, tanh_approx(q1 + acc[mi][ni][3]), phi);
        }
        plo += __shfl_xor_sync(~0u, plo, 1);
        plo += __shfl_xor_sync(~0u, plo, 2);
        phi += __shfl_xor_sync(~0u, phi, 1);
        phi += __shfl_xor_sync(~0u, phi, 2);
        if (tig == 0) {
            int row = wm * 64 + mi * 16 + g;
            s_part[wn * 128 + row] = plo;
            s_part[wn * 128 + row + 8] = phi;
        }
    }
    __syncthreads();
    if (tid < 128) {
        float s = s_part[tid] + s_part[128 + tid] + s_part[256 + tid] + s_part[384 + tid];
        sc2[(size_t)nh * BB * TT + (size_t)b * TT + t0 + tid] = s;
    }
}

// ---------------- kernel 4: masked softmax over T per batch (sums the two halves) ----------------
// Mask dtype is auto-detected: bool arrays may be materialized by the harness as
// int32 (values 0/1) or as 1-byte bools. If the first 64 words are all <= 1, it is
// int32 (a genuine random byte-mask would need 192 random bits to all be zero).
__global__ void softmax_kernel(const float* __restrict__ sc2, const void* __restrict__ maskp,
                               float* __restrict__ w) {
    int b = blockIdx.x;
    __shared__ float sh[TT];
    __shared__ float red[32];
    __shared__ int is_i32_sh;
    int tid = threadIdx.x;  // 256
    if (tid == 0) {
        const uint32_t* mw = (const uint32_t*)maskp;
        int ok = 1;
        for (int i = 0; i < 64; i++)
            if (mw[i] > 1u) { ok = 0; break; }
        is_i32_sh = ok;
    }
    __syncthreads();
    int is_i32 = is_i32_sh;
    const int* mi32 = (const int*)maskp;
    const unsigned char* mu8 = (const unsigned char*)maskp;

    const float* s0 = sc2 + (size_t)b * TT;
    const float* s1 = sc2 + (size_t)BB * TT + (size_t)b * TT;
    float lm = -3e38f;
    for (int t = tid; t < TT; t += 256) {
        size_t idx = (size_t)b * TT + t;
        bool mv = is_i32 ? (mi32[idx] != 0) : (mu8[idx] != 0);
        float sc = mv ? (s0[t] + s1[t]) : -1e9f;
        sh[t] = sc;
        lm = fmaxf(lm, sc);
    }
#pragma unroll
    for (int o = 16; o; o >>= 1) lm = fmaxf(lm, __shfl_xor_sync(~0u, lm, o));
    if ((tid & 31) == 0) red[tid >> 5] = lm;
    __syncthreads();
    if (tid < 32) {
        float v = (tid < 8) ? red[tid] : -3e38f;
#pragma unroll
        for (int o = 4; o; o >>= 1) v = fmaxf(v, __shfl_xor_sync(~0u, v, o));
        if (tid == 0) red[0] = v;
    }
    __syncthreads();
    float M = red[0];
    float ls = 0.f;
    for (int t = tid; t < TT; t += 256) {
        float p = __expf(sh[t] - M);
        sh[t] = p;
        ls += p;
    }
    __syncthreads();
#pragma unroll
    for (int o = 16; o; o >>= 1) ls += __shfl_xor_sync(~0u, ls, o);
    if ((tid & 31) == 0) red[tid >> 5] = ls;
    __syncthreads();
    if (tid < 32) {
        float v = (tid < 8) ? red[tid] : 0.f;
#pragma unroll
        for (int o = 4; o; o >>= 1) v += __shfl_xor_sync(~0u, v, o);
        if (tid == 0) red[0] = v;
    }
    __syncthreads();
    float inv = 1.f / red[0];
    for (int t = tid; t < TT; t += 256) w[(size_t)b * TT + t] = sh[t] * inv;
}

// ---------------- kernel 5: ctx[b,e] = sum_t w[b,t] * h_enc[b,t,e] ----------------
__global__ void ctx_kernel(const float* __restrict__ henc, const float* __restrict__ w,
                           float* __restrict__ ctx) {
    int b = blockIdx.y;
    int e = blockIdx.x * 256 + threadIdx.x;  // grid.x = 2
    __shared__ float ws[TT];
    for (int t = threadIdx.x; t < TT; t += 256) ws[t] = w[(size_t)b * TT + t];
    __syncthreads();
    const float* base = henc + (size_t)b * TT * DE + e;
    float acc = 0.f;
#pragma unroll 8
    for (int t = 0; t < TT; t++) acc = fmaf(ws[t], base[(size_t)t * DE], acc);
    ctx[(size_t)b * DE + e] = acc;
}

// ---------------- host launcher ----------------
extern "C" void kernel_launch(void* const* d_in, const int* in_sizes, int n_in,
                              void* d_out, int out_size) {
    const float* h_enc = (const float*)d_in[0];
    const float* h_dec = (const float*)d_in[1];
    const float* Wq_w  = (const float*)d_in[2];
    const float* Wq_b  = (const float*)d_in[3];
    const float* Wk_w  = (const float*)d_in[4];
    const float* Wk_b  = (const float*)d_in[5];
    const float* v_w   = (const float*)d_in[6];
    const void*  mask  = (const void*)d_in[7];

    float* out = (float*)d_out;
    float* ctx = out;                 // [B, 512]
    float* w   = out + BB * DE;       // [B, 4096]

    void *p_henc, *p_wk, *p_qpk, *p_sc2;
    cudaGetSymbolAddress(&p_henc, g_henc_bf);
    cudaGetSymbolAddress(&p_wk, g_wk_bf);
    cudaGetSymbolAddress(&p_qpk, g_qpk);
    cudaGetSymbolAddress(&p_sc2, g_scores2);

    cudaFuncSetAttribute(gemm_score_kernel, cudaFuncAttributeMaxDynamicSharedMemorySize, GEMM_SMEM);

    long n4 = (long)BB * TT * DE / 4;  // 33554432
    convert_kernel<<<(unsigned)(n4 / 256), 256>>>(h_enc, (__nv_bfloat16*)p_henc, n4);
    convert_kernel<<<(DA * DE / 4) / 256, 256>>>(Wk_w, (__nv_bfloat16*)p_wk, DA * DE / 4);
    qpk_kernel<<<BB, 256>>>(h_dec, Wq_w, Wq_b, Wk_b, (float*)p_qpk);
    gemm_score_kernel<<<BB * 32 * 2, 256, GEMM_SMEM>>>(
        (const __nv_bfloat16*)p_henc, (const __nv_bfloat16*)p_wk,
        (const float*)p_qpk, v_w, (float*)p_sc2);
    softmax_kernel<<<BB, 256>>>((const float*)p_sc2, mask, w);
    ctx_kernel<<<dim3(2, BB), 256>>>(h_enc, w, ctx);
}

// round 8
// speedup vs baseline: 1.7417x; 1.7417x over previous
#include <cuda_runtime.h>
#include <cuda_bf16.h>
#include <cstdint>
#include <cstddef>

// Problem dims (fixed by the reference)
#define BB   64
#define TT   4096
#define DE   512
#define DA   256

// ---------------- scratch (device globals; no allocation in kernel_launch) ----------------
__device__ __nv_bfloat16 g_wk_bf[DA * DE];                  // 256 KB
__device__ float         g_qpk[BB * DA];                    // q + Wq_b + Wk_b
__device__ float         g_scores2[2][(size_t)BB * TT];     // per-N-half partial scores
__device__ float         g_ctx_part[8][(size_t)BB * DE];    // T-split partial ctx

// ---------------- PTX helpers (compute_103-safe: no tcgen05/TMEM) ----------------
__device__ __forceinline__ uint32_t smem_u32(const void* p) {
    uint32_t a;
    asm("{ .reg .u64 t; cvta.to.shared.u64 t, %1; cvt.u32.u64 %0, t; }" : "=r"(a) : "l"(p));
    return a;
}
__device__ __forceinline__ void cp_async16(uint32_t dst, const void* src) {
    asm volatile("cp.async.cg.shared.global [%0], [%1], 16;" :: "r"(dst), "l"(src) : "memory");
}
__device__ __forceinline__ void cp_commit() {
    asm volatile("cp.async.commit_group;" ::: "memory");
}
template <int N>
__device__ __forceinline__ void cp_wait() {
    asm volatile("cp.async.wait_group %0;" :: "n"(N) : "memory");
}
__device__ __forceinline__ void ldmatrix_x4(uint32_t* r, uint32_t addr) {
    asm volatile("ldmatrix.sync.aligned.m8n8.x4.shared.b16 {%0,%1,%2,%3}, [%4];"
                 : "=r"(r[0]), "=r"(r[1]), "=r"(r[2]), "=r"(r[3]) : "r"(addr));
}
__device__ __forceinline__ void ldmatrix_x2(uint32_t* r, uint32_t addr) {
    asm volatile("ldmatrix.sync.aligned.m8n8.x2.shared.b16 {%0,%1}, [%2];"
                 : "=r"(r[0]), "=r"(r[1]) : "r"(addr));
}
__device__ __forceinline__ void mma16816(float* c, const uint32_t* a, const uint32_t* b) {
    asm volatile(
        "mma.sync.aligned.m16n8k16.row.col.f32.bf16.bf16.f32 "
        "{%0,%1,%2,%3}, {%4,%5,%6,%7}, {%8,%9}, {%0,%1,%2,%3};"
        : "+f"(c[0]), "+f"(c[1]), "+f"(c[2]), "+f"(c[3])
        : "r"(a[0]), "r"(a[1]), "r"(a[2]), "r"(a[3]), "r"(b[0]), "r"(b[1]));
}
__device__ __forceinline__ float tanh_approx(float x) {
    float y;
    asm("tanh.approx.f32 %0, %1;" : "=f"(y) : "f"(x));
    return y;
}
__device__ __forceinline__ uint32_t pack_bf16x2(float lo, float hi) {
    __nv_bfloat162 p = __floats2bfloat162_rn(lo, hi);
    return *reinterpret_cast<uint32_t*>(&p);
}

// SW128 swizzle (Swizzle<3,4,3>) on tile-local byte offsets, rows = 128B.
// Preserves bits [0:3], so 8B-aligned stores inside a 16B block stay consistent.
#define SWZ(o) ((o) ^ (((o) >> 3) & 0x70))

// ---------------- kernel 1: f32 -> bf16 convert (Wk only; h_enc is fused into GEMM) ----------------
__global__ void convert_kernel(const float* __restrict__ src, __nv_bfloat16* __restrict__ dst, long n4) {
    long i = (long)blockIdx.x * blockDim.x + threadIdx.x;
    if (i >= n4) return;
    float4 v = reinterpret_cast<const float4*>(src)[i];
    uint2 o;
    o.x = pack_bf16x2(v.x, v.y);
    o.y = pack_bf16x2(v.z, v.w);
    reinterpret_cast<uint2*>(dst)[i] = o;
}

// ---------------- kernel 2: qpk[b,a] = h_dec[b]·Wq[a] + Wq_b[a] + Wk_b[a] ----------------
__global__ void qpk_kernel(const float* __restrict__ hdec, const float* __restrict__ Wq,
                           const float* __restrict__ Wqb, const float* __restrict__ Wkb,
                           float* __restrict__ qpk) {
    int b = blockIdx.x;
    int a = threadIdx.x;  // 256
    __shared__ float h[DE];
    for (int e = threadIdx.x; e < DE; e += 256) h[e] = hdec[b * DE + e];
    __syncthreads();
    const float* w = Wq + (size_t)a * DE;
    float acc = 0.f;
#pragma unroll 8
    for (int e = 0; e < DE; e++) acc = fmaf(h[e], w[e], acc);
    qpk[b * DA + a] = acc + Wqb[a] + Wkb[a];
}

// ---------------- kernel 3: mma.sync GEMM + fused f32->bf16 A-convert + score epilogue ----------------
// CTA tile: M=128 (rows of one b), N=128 (one half of DA), K=512 in 8 chunks of 64.
// A is read from f32 h_enc directly: LDG float4 -> cvt -> STS bf16 (register double-buffer,
// two halves interleaved with the MMA halves). B (Wk, bf16) stays cp.async double-buffered.
#define SM_PART   0                 // float s_part[4][128] = 2048 B
#define SM_V      2048              // float sv[128]
#define SM_Q      2560              // float sq[128]
#define SM_A(st)  (4096 + (st) * 16384)       // A stage: 128 rows x 128 B (bf16)
#define SM_B(st)  (36864 + (st) * 16384)      // B stage: 128 rows x 128 B (bf16)
#define GEMM_SMEM 69632

__global__ void __launch_bounds__(256, 2) gemm_score_kernel(
    const float* __restrict__ A,            // [B*T, 512] f32 (h_enc)
    const __nv_bfloat16* __restrict__ Bm,   // [256, 512] bf16 (Wk)
    const float* __restrict__ qpk,
    const float* __restrict__ v_w,
    float* __restrict__ sc2) {              // [2][B*T]
    extern __shared__ char smem[];
    uint32_t sb = smem_u32(smem);
    int tid = threadIdx.x;
    int wid = tid >> 5, lane = tid & 31;
    int wm = wid >> 2, wn = wid & 3;
    int g = lane >> 2, tig = lane & 3;

    // grid: bx = (b*32 + mt)*2 + nh  -> adjacent CTAs share the A tile (L2 reuse)
    int nh = blockIdx.x & 1;
    int mt = (blockIdx.x >> 1) & 31;
    int b  = blockIdx.x >> 6;
    int t0 = mt << 7;
    size_t m0 = ((size_t)b * 32 + mt) * 128;

    if (tid < 128) {
        ((float*)(smem + SM_V))[tid] = v_w[nh * 128 + tid];
        ((float*)(smem + SM_Q))[tid] = qpk[b * DA + nh * 128 + tid];
    }

    const __nv_bfloat16* Bh = Bm + (size_t)(nh * 128) * DE;
    const float* Abase = A + m0 * DE;

    // A load geometry: chunk = 128 rows x 64 f32; 256 threads x 8 float4.
    // i-th float4 of this thread: row = (tid>>4) + i*16, col4 = tid&15.
    int arow0 = tid >> 4;
    int acol4 = tid & 15;
    uint32_t asw[8];
#pragma unroll
    for (int i = 0; i < 8; i++)
        asw[i] = (uint32_t)SWZ((arow0 + i * 16) * 128 + acol4 * 8);

    auto ldgA = [&](int kc, int i0, float4* st) {
        const float4* src = (const float4*)(Abase + (size_t)kc * 64);
        // float4 index within row: 512 f32 = 128 float4 per full row; chunk offset handled above
#pragma unroll
        for (int i = 0; i < 4; i++) {
            int row = arow0 + (i0 + i) * 16;
            st[i] = src[(size_t)row * 128 + acol4];
        }
    };
    auto stsA = [&](int stg, int i0, const float4* st) {
        char* dst = smem + SM_A(stg);
#pragma unroll
        for (int i = 0; i < 4; i++) {
            uint2 o;
            o.x = pack_bf16x2(st[i].x, st[i].y);
            o.y = pack_bf16x2(st[i].z, st[i].w);
            *reinterpret_cast<uint2*>(dst + asw[i0 + i]) = o;
        }
    };
    auto issueB = [&](int kc, int stg) {
        uint32_t bS = sb + SM_B(stg);
        const __nv_bfloat16* bb = Bh + kc * 64;
#pragma unroll
        for (int i = 0; i < 4; i++) {
            int c = tid + i * 256;
            int row = c >> 3, cc = c & 7;
            cp_async16(bS + SWZ(row * 128 + cc * 16), bb + (size_t)row * DE + cc * 8);
        }
        cp_commit();
    };

    float acc[4][4][4];
#pragma unroll
    for (int mi = 0; mi < 4; mi++)
#pragma unroll
        for (int ni = 0; ni < 4; ni++)
#pragma unroll
            for (int e = 0; e < 4; e++) acc[mi][ni][e] = 0.f;

    // ldmatrix per-lane selectors
    int arow = wm * 64 + (lane & 15);
    int acb  = lane >> 4;
    int brow = wn * 32 + (lane & 7);
    int bkb  = (lane >> 3) & 1;

    // ---- prologue: fill stage 0 ----
    {
        issueB(0, 0);
        float4 st[4];
        ldgA(0, 0, st); stsA(0, 0, st);
        ldgA(0, 4, st); stsA(0, 4, st);
        cp_wait<0>();
    }
    __syncthreads();

#pragma unroll 1
    for (int kc = 0; kc < 8; kc++) {
        int cur = kc & 1, nxt = cur ^ 1;
        float4 st0[4], st1[4];
        if (kc < 7) {
            issueB(kc + 1, nxt);
            ldgA(kc + 1, 0, st0);
        }
        uint32_t aS = sb + SM_A(cur), bS = sb + SM_B(cur);
#pragma unroll
        for (int ks = 0; ks < 2; ks++) {
            uint32_t af[4][4], bf_[4][2];
#pragma unroll
            for (int mi = 0; mi < 4; mi++)
                ldmatrix_x4(af[mi], aS + SWZ((arow + mi * 16) * 128 + ks * 32 + acb * 16));
#pragma unroll
            for (int ni = 0; ni < 4; ni++)
                ldmatrix_x2(bf_[ni], bS + SWZ((brow + ni * 8) * 128 + ks * 32 + bkb * 16));
#pragma unroll
            for (int mi = 0; mi < 4; mi++)
#pragma unroll
                for (int ni = 0; ni < 4; ni++)
                    mma16816(acc[mi][ni], af[mi], bf_[ni]);
        }
        if (kc < 7) {
            stsA(nxt, 0, st0);
            ldgA(kc + 1, 4, st1);
        }
#pragma unroll
        for (int ks = 2; ks < 4; ks++) {
            uint32_t af[4][4], bf_[4][2];
#pragma unroll
            for (int mi = 0; mi < 4; mi++)
                ldmatrix_x4(af[mi], aS + SWZ((arow + mi * 16) * 128 + ks * 32 + acb * 16));
#pragma unroll
            for (int ni = 0; ni < 4; ni++)
                ldmatrix_x2(bf_[ni], bS + SWZ((brow + ni * 8) * 128 + ks * 32 + bkb * 16));
#pragma unroll
            for (int mi = 0; mi < 4; mi++)
#pragma unroll
                for (int ni = 0; ni < 4; ni++)
                    mma16816(acc[mi][ni], af[mi], bf_[ni]);
        }
        if (kc < 7) {
            stsA(nxt, 4, st1);
            cp_wait<0>();
        }
        __syncthreads();
    }

    // ---- epilogue: partial score = sum over this half's a of v*tanh(qpk + k) ----
    const float* sv = (const float*)(smem + SM_V);
    const float* sq = (const float*)(smem + SM_Q);
    float* s_part = (float*)(smem + SM_PART);

#pragma unroll
    for (int mi = 0; mi < 4; mi++) {
        float plo = 0.f, phi = 0.f;
#pragma unroll
        for (int ni = 0; ni < 4; ni++) {
            int n = wn * 32 + ni * 8 + tig * 2;
            float v0 = sv[n], v1 = sv[n + 1], q0 = sq[n], q1 = sq[n + 1];
            plo = fmaf(v0, tanh_approx(q0 + acc[mi][ni][0]), plo);
            plo = fmaf(v1, tanh_approx(q1 + acc[mi][ni][1]), plo);
            phi = fmaf(v0, tanh_approx(q0 + acc[mi][ni][2]), phi);
            phi = fmaf(v1, tanh_approx(q1 + acc[mi][ni][3]), phi);
        }
        plo += __shfl_xor_sync(~0u, plo, 1);
        plo += __shfl_xor_sync(~0u, plo, 2);
        phi += __shfl_xor_sync(~0u, phi, 1);
        phi += __shfl_xor_sync(~0u, phi, 2);
        if (tig == 0) {
            int row = wm * 64 + mi * 16 + g;
            s_part[wn * 128 + row] = plo;
            s_part[wn * 128 + row + 8] = phi;
        }
    }
    __syncthreads();
    if (tid < 128) {
        float s = s_part[tid] + s_part[128 + tid] + s_part[256 + tid] + s_part[384 + tid];
        sc2[(size_t)nh * BB * TT + (size_t)b * TT + t0 + tid] = s;
    }
}

// ---------------- kernel 4: masked softmax over T per batch (sums the two halves) ----------------
__global__ void softmax_kernel(const float* __restrict__ sc2, const void* __restrict__ maskp,
                               float* __restrict__ w) {
    int b = blockIdx.x;
    __shared__ float sh[TT];
    __shared__ float red[32];
    __shared__ int is_i32_sh;
    int tid = threadIdx.x;  // 256
    if (tid == 0) {
        const uint32_t* mw = (const uint32_t*)maskp;
        int ok = 1;
        for (int i = 0; i < 64; i++)
            if (mw[i] > 1u) { ok = 0; break; }
        is_i32_sh = ok;
    }
    __syncthreads();
    int is_i32 = is_i32_sh;
    const int* mi32 = (const int*)maskp;
    const unsigned char* mu8 = (const unsigned char*)maskp;

    const float* s0 = sc2 + (size_t)b * TT;
    const float* s1 = sc2 + (size_t)BB * TT + (size_t)b * TT;
    float lm = -3e38f;
    for (int t = tid; t < TT; t += 256) {
        size_t idx = (size_t)b * TT + t;
        bool mv = is_i32 ? (mi32[idx] != 0) : (mu8[idx] != 0);
        float sc = mv ? (s0[t] + s1[t]) : -1e9f;
        sh[t] = sc;
        lm = fmaxf(lm, sc);
    }
#pragma unroll
    for (int o = 16; o; o >>= 1) lm = fmaxf(lm, __shfl_xor_sync(~0u, lm, o));
    if ((tid & 31) == 0) red[tid >> 5] = lm;
    __syncthreads();
    if (tid < 32) {
        float v = (tid < 8) ? red[tid] : -3e38f;
#pragma unroll
        for (int o = 4; o; o >>= 1) v = fmaxf(v, __shfl_xor_sync(~0u, v, o));
        if (tid == 0) red[0] = v;
    }
    __syncthreads();
    float M = red[0];
    float ls = 0.f;
    for (int t = tid; t < TT; t += 256) {
        float p = __expf(sh[t] - M);
        sh[t] = p;
        ls += p;
    }
    __syncthreads();
#pragma unroll
    for (int o = 16; o; o >>= 1) ls += __shfl_xor_sync(~0u, ls, o);
    if ((tid & 31) == 0) red[tid >> 5] = ls;
    __syncthreads();
    if (tid < 32) {
        float v = (tid < 8) ? red[tid] : 0.f;
#pragma unroll
        for (int o = 4; o; o >>= 1) v += __shfl_xor_sync(~0u, v, o);
        if (tid == 0) red[0] = v;
    }
    __syncthreads();
    float inv = 1.f / red[0];
    for (int t = tid; t < TT; t += 256) w[(size_t)b * TT + t] = sh[t] * inv;
}

// ---------------- kernel 5a: partial ctx over T-chunks ----------------
// grid (2, BB, 8): each block covers 256 e-columns x 512 timesteps.
__global__ void ctx_part_kernel(const float* __restrict__ henc, const float* __restrict__ w,
                                float* __restrict__ part) {
    int b = blockIdx.y;
    int tc = blockIdx.z;
    int e = blockIdx.x * 256 + threadIdx.x;
    __shared__ float ws[512];
    const float* wp = w + (size_t)b * TT + tc * 512;
    for (int t = threadIdx.x; t < 512; t += 256) ws[t] = wp[t];
    __syncthreads();
    const float* base = henc + (size_t)b * TT * DE + (size_t)tc * 512 * DE + e;
    float acc = 0.f;
#pragma unroll 8
    for (int t = 0; t < 512; t++) acc = fmaf(ws[t], base[(size_t)t * DE], acc);
    part[((size_t)tc * BB + b) * DE + e] = acc;
}

// ---------------- kernel 5b: reduce partials ----------------
__global__ void ctx_reduce_kernel(const float* __restrict__ part, float* __restrict__ ctx) {
    int i = blockIdx.x * 256 + threadIdx.x;  // BB*DE = 32768
    float s = 0.f;
#pragma unroll
    for (int p = 0; p < 8; p++) s += part[(size_t)p * BB * DE + i];
    ctx[i] = s;
}

// ---------------- host launcher ----------------
extern "C" void kernel_launch(void* const* d_in, const int* in_sizes, int n_in,
                              void* d_out, int out_size) {
    const float* h_enc = (const float*)d_in[0];
    const float* h_dec = (const float*)d_in[1];
    const float* Wq_w  = (const float*)d_in[2];
    const float* Wq_b  = (const float*)d_in[3];
    const float* Wk_w  = (const float*)d_in[4];
    const float* Wk_b  = (const float*)d_in[5];
    const float* v_w   = (const float*)d_in[6];
    const void*  mask  = (const void*)d_in[7];

    float* out = (float*)d_out;
    float* ctx = out;                 // [B, 512]
    float* w   = out + BB * DE;       // [B, 4096]

    void *p_wk, *p_qpk, *p_sc2, *p_part;
    cudaGetSymbolAddress(&p_wk, g_wk_bf);
    cudaGetSymbolAddress(&p_qpk, g_qpk);
    cudaGetSymbolAddress(&p_sc2, g_scores2);
    cudaGetSymbolAddress(&p_part, g_ctx_part);

    cudaFuncSetAttribute(gemm_score_kernel, cudaFuncAttributeMaxDynamicSharedMemorySize, GEMM_SMEM);

    convert_kernel<<<(DA * DE / 4) / 256, 256>>>(Wk_w, (__nv_bfloat16*)p_wk, DA * DE / 4);
    qpk_kernel<<<BB, 256>>>(h_dec, Wq_w, Wq_b, Wk_b, (float*)p_qpk);
    gemm_score_kernel<<<BB * 32 * 2, 256, GEMM_SMEM>>>(
        h_enc, (const __nv_bfloat16*)p_wk,
        (const float*)p_qpk, v_w, (float*)p_sc2);
    softmax_kernel<<<BB, 256>>>((const float*)p_sc2, mask, w);
    ctx_part_kernel<<<dim3(2, BB, 8), 256>>>(h_enc, w, (float*)p_part);
    ctx_reduce_kernel<<<BB * DE / 256, 256>>>((const float*)p_part, ctx);
}

// round 9
// speedup vs baseline: 1.7859x; 1.0254x over previous
#include <cuda_runtime.h>
#include <cuda_bf16.h>
#include <cstdint>
#include <cstddef>

// Problem dims (fixed by the reference)
#define BB   64
#define TT   4096
#define DE   512
#define DA   256

// ---------------- scratch (device globals; no allocation in kernel_launch) ----------------
__device__ __nv_bfloat16 g_wk_bf[DA * DE];                  // 256 KB
__device__ float         g_qpk[BB * DA];                    // q + Wq_b + Wk_b
__device__ float         g_scores2[2][(size_t)BB * TT];     // per-N-half partial scores
__device__ float         g_ctx_part[8][(size_t)BB * DE];    // T-split partial ctx
__device__ float         g_psum[8][BB];                     // T-split partial exp-sums

// ---------------- PTX helpers (compute_103-safe: no tcgen05/TMEM) ----------------
__device__ __forceinline__ uint32_t smem_u32(const void* p) {
    uint32_t a;
    asm("{ .reg .u64 t; cvta.to.shared.u64 t, %1; cvt.u32.u64 %0, t; }" : "=r"(a) : "l"(p));
    return a;
}
__device__ __forceinline__ void cp_async16(uint32_t dst, const void* src) {
    asm volatile("cp.async.cg.shared.global [%0], [%1], 16;" :: "r"(dst), "l"(src) : "memory");
}
__device__ __forceinline__ void cp_commit() {
    asm volatile("cp.async.commit_group;" ::: "memory");
}
template <int N>
__device__ __forceinline__ void cp_wait() {
    asm volatile("cp.async.wait_group %0;" :: "n"(N) : "memory");
}
__device__ __forceinline__ void ldmatrix_x4(uint32_t* r, uint32_t addr) {
    asm volatile("ldmatrix.sync.aligned.m8n8.x4.shared.b16 {%0,%1,%2,%3}, [%4];"
                 : "=r"(r[0]), "=r"(r[1]), "=r"(r[2]), "=r"(r[3]) : "r"(addr));
}
__device__ __forceinline__ void ldmatrix_x2(uint32_t* r, uint32_t addr) {
    asm volatile("ldmatrix.sync.aligned.m8n8.x2.shared.b16 {%0,%1}, [%2];"
                 : "=r"(r[0]), "=r"(r[1]) : "r"(addr));
}
__device__ __forceinline__ void mma16816(float* c, const uint32_t* a, const uint32_t* b) {
    asm volatile(
        "mma.sync.aligned.m16n8k16.row.col.f32.bf16.bf16.f32 "
        "{%0,%1,%2,%3}, {%4,%5,%6,%7}, {%8,%9}, {%0,%1,%2,%3};"
        : "+f"(c[0]), "+f"(c[1]), "+f"(c[2]), "+f"(c[3])
        : "r"(a[0]), "r"(a[1]), "r"(a[2]), "r"(a[3]), "r"(b[0]), "r"(b[1]));
}
__device__ __forceinline__ float tanh_approx(float x) {
    float y;
    asm("tanh.approx.f32 %0, %1;" : "=f"(y) : "f"(x));
    return y;
}
__device__ __forceinline__ uint32_t pack_bf16x2(float lo, float hi) {
    __nv_bfloat162 p = __floats2bfloat162_rn(lo, hi);
    return *reinterpret_cast<uint32_t*>(&p);
}

// SW128 swizzle (Swizzle<3,4,3>) on tile-local byte offsets, rows = 128B.
#define SWZ(o) ((o) ^ (((o) >> 3) & 0x70))

// ---------------- kernel 1: f32 -> bf16 convert (Wk only) ----------------
__global__ void convert_kernel(const float* __restrict__ src, __nv_bfloat16* __restrict__ dst, long n4) {
    long i = (long)blockIdx.x * blockDim.x + threadIdx.x;
    if (i >= n4) return;
    float4 v = reinterpret_cast<const float4*>(src)[i];
    uint2 o;
    o.x = pack_bf16x2(v.x, v.y);
    o.y = pack_bf16x2(v.z, v.w);
    reinterpret_cast<uint2*>(dst)[i] = o;
}

// ---------------- kernel 2: qpk[b,a] = h_dec[b]·Wq[a] + Wq_b[a] + Wk_b[a] ----------------
__global__ void qpk_kernel(const float* __restrict__ hdec, const float* __restrict__ Wq,
                           const float* __restrict__ Wqb, const float* __restrict__ Wkb,
                           float* __restrict__ qpk) {
    int b = blockIdx.x;
    int a = threadIdx.x;  // 256
    __shared__ float h[DE];
    for (int e = threadIdx.x; e < DE; e += 256) h[e] = hdec[b * DE + e];
    __syncthreads();
    const float* w = Wq + (size_t)a * DE;
    float acc = 0.f;
#pragma unroll 8
    for (int e = 0; e < DE; e++) acc = fmaf(h[e], w[e], acc);
    qpk[b * DA + a] = acc + Wqb[a] + Wkb[a];
}

// ---------------- kernel 3: mma.sync GEMM + fused f32->bf16 A-convert + score epilogue ----------------
// (unchanged from R7 — passing at ~190us; next round's target)
#define SM_PART   0
#define SM_V      2048
#define SM_Q      2560
#define SM_A(st)  (4096 + (st) * 16384)
#define SM_B(st)  (36864 + (st) * 16384)
#define GEMM_SMEM 69632

__global__ void __launch_bounds__(256, 2) gemm_score_kernel(
    const float* __restrict__ A,            // [B*T, 512] f32 (h_enc)
    const __nv_bfloat16* __restrict__ Bm,   // [256, 512] bf16 (Wk)
    const float* __restrict__ qpk,
    const float* __restrict__ v_w,
    float* __restrict__ sc2) {              // [2][B*T]
    extern __shared__ char smem[];
    uint32_t sb = smem_u32(smem);
    int tid = threadIdx.x;
    int wid = tid >> 5, lane = tid & 31;
    int wm = wid >> 2, wn = wid & 3;
    int g = lane >> 2, tig = lane & 3;

    int nh = blockIdx.x & 1;
    int mt = (blockIdx.x >> 1) & 31;
    int b  = blockIdx.x >> 6;
    int t0 = mt << 7;
    size_t m0 = ((size_t)b * 32 + mt) * 128;

    if (tid < 128) {
        ((float*)(smem + SM_V))[tid] = v_w[nh * 128 + tid];
        ((float*)(smem + SM_Q))[tid] = qpk[b * DA + nh * 128 + tid];
    }

    const __nv_bfloat16* Bh = Bm + (size_t)(nh * 128) * DE;
    const float* Abase = A + m0 * DE;

    int arow0 = tid >> 4;
    int acol4 = tid & 15;
    uint32_t asw[8];
#pragma unroll
    for (int i = 0; i < 8; i++)
        asw[i] = (uint32_t)SWZ((arow0 + i * 16) * 128 + acol4 * 8);

    auto ldgA = [&](int kc, int i0, float4* st) {
        const float4* src = (const float4*)(Abase + (size_t)kc * 64);
#pragma unroll
        for (int i = 0; i < 4; i++) {
            int row = arow0 + (i0 + i) * 16;
            st[i] = src[(size_t)row * 128 + acol4];
        }
    };
    auto stsA = [&](int stg, int i0, const float4* st) {
        char* dst = smem + SM_A(stg);
#pragma unroll
        for (int i = 0; i < 4; i++) {
            uint2 o;
            o.x = pack_bf16x2(st[i].x, st[i].y);
            o.y = pack_bf16x2(st[i].z, st[i].w);
            *reinterpret_cast<uint2*>(dst + asw[i0 + i]) = o;
        }
    };
    auto issueB = [&](int kc, int stg) {
        uint32_t bS = sb + SM_B(stg);
        const __nv_bfloat16* bb = Bh + kc * 64;
#pragma unroll
        for (int i = 0; i < 4; i++) {
            int c = tid + i * 256;
            int row = c >> 3, cc = c & 7;
            cp_async16(bS + SWZ(row * 128 + cc * 16), bb + (size_t)row * DE + cc * 8);
        }
        cp_commit();
    };

    float acc[4][4][4];
#pragma unroll
    for (int mi = 0; mi < 4; mi++)
#pragma unroll
        for (int ni = 0; ni < 4; ni++)
#pragma unroll
            for (int e = 0; e < 4; e++) acc[mi][ni][e] = 0.f;

    int arow = wm * 64 + (lane & 15);
    int acb  = lane >> 4;
    int brow = wn * 32 + (lane & 7);
    int bkb  = (lane >> 3) & 1;

    {
        issueB(0, 0);
        float4 st[4];
        ldgA(0, 0, st); stsA(0, 0, st);
        ldgA(0, 4, st); stsA(0, 4, st);
        cp_wait<0>();
    }
    __syncthreads();

#pragma unroll 1
    for (int kc = 0; kc < 8; kc++) {
        int cur = kc & 1, nxt = cur ^ 1;
        float4 st0[4], st1[4];
        if (kc < 7) {
            issueB(kc + 1, nxt);
            ldgA(kc + 1, 0, st0);
        }
        uint32_t aS = sb + SM_A(cur), bS = sb + SM_B(cur);
#pragma unroll
        for (int ks = 0; ks < 2; ks++) {
            uint32_t af[4][4], bf_[4][2];
#pragma unroll
            for (int mi = 0; mi < 4; mi++)
                ldmatrix_x4(af[mi], aS + SWZ((arow + mi * 16) * 128 + ks * 32 + acb * 16));
#pragma unroll
            for (int ni = 0; ni < 4; ni++)
                ldmatrix_x2(bf_[ni], bS + SWZ((brow + ni * 8) * 128 + ks * 32 + bkb * 16));
#pragma unroll
            for (int mi = 0; mi < 4; mi++)
#pragma unroll
                for (int ni = 0; ni < 4; ni++)
                    mma16816(acc[mi][ni], af[mi], bf_[ni]);
        }
        if (kc < 7) {
            stsA(nxt, 0, st0);
            ldgA(kc + 1, 4, st1);
        }
#pragma unroll
        for (int ks = 2; ks < 4; ks++) {
            uint32_t af[4][4], bf_[4][2];
#pragma unroll
            for (int mi = 0; mi < 4; mi++)
                ldmatrix_x4(af[mi], aS + SWZ((arow + mi * 16) * 128 + ks * 32 + acb * 16));
#pragma unroll
            for (int ni = 0; ni < 4; ni++)
                ldmatrix_x2(bf_[ni], bS + SWZ((brow + ni * 8) * 128 + ks * 32 + bkb * 16));
#pragma unroll
            for (int mi = 0; mi < 4; mi++)
#pragma unroll
                for (int ni = 0; ni < 4; ni++)
                    mma16816(acc[mi][ni], af[mi], bf_[ni]);
        }
        if (kc < 7) {
            stsA(nxt, 4, st1);
            cp_wait<0>();
        }
        __syncthreads();
    }

    const float* sv = (const float*)(smem + SM_V);
    const float* sq = (const float*)(smem + SM_Q);
    float* s_part = (float*)(smem + SM_PART);

#pragma unroll
    for (int mi = 0; mi < 4; mi++) {
        float plo = 0.f, phi = 0.f;
#pragma unroll
        for (int ni = 0; ni < 4; ni++) {
            int n = wn * 32 + ni * 8 + tig * 2;
            float v0 = sv[n], v1 = sv[n + 1], q0 = sq[n], q1 = sq[n + 1];
            plo = fmaf(v0, tanh_approx(q0 + acc[mi][ni][0]), plo);
            plo = fmaf(v1, tanh_approx(q1 + acc[mi][ni][1]), plo);
            phi = fmaf(v0, tanh_approx(q0 + acc[mi][ni][2]), phi);
            phi = fmaf(v1, tanh_approx(q1 + acc[mi][ni][3]), phi);
        }
        plo += __shfl_xor_sync(~0u, plo, 1);
        plo += __shfl_xor_sync(~0u, plo, 2);
        phi += __shfl_xor_sync(~0u, phi, 1);
        phi += __shfl_xor_sync(~0u, phi, 2);
        if (tig == 0) {
            int row = wm * 64 + mi * 16 + g;
            s_part[wn * 128 + row] = plo;
            s_part[wn * 128 + row + 8] = phi;
        }
    }
    __syncthreads();
    if (tid < 128) {
        float s = s_part[tid] + s_part[128 + tid] + s_part[256 + tid] + s_part[384 + tid];
        sc2[(size_t)nh * BB * TT + (size_t)b * TT + t0 + tid] = s;
    }
}

// ---------------- kernel 4: fused exp/mask + partial ctx over T-chunks ----------------
// Scores are tiny (|s| < ~2): exp without max-subtraction is exact-safe in f32,
// so the softmax normalization is deferred to the finalize kernel.
// grid (2, BB, 8): block covers 256 e-columns x 512 timesteps.
// blockIdx.x==0 additionally writes unnormalized p into the w output buffer and
// the chunk exp-sum into psum.
__global__ void ctx_part_kernel(const float* __restrict__ henc, const float* __restrict__ sc2,
                                const void* __restrict__ maskp,
                                float* __restrict__ w, float* __restrict__ part,
                                float* __restrict__ psum) {
    int b = blockIdx.y;
    int tc = blockIdx.z;
    int e = blockIdx.x * 256 + threadIdx.x;
    int tid = threadIdx.x;
    __shared__ float ws[512];
    __shared__ float red[8];
    __shared__ int is_i32_sh;

    if (tid == 0) {
        // mask dtype auto-detect: int32 0/1 vs 1-byte bool (see R5 note)
        const uint32_t* mw = (const uint32_t*)maskp;
        int ok = 1;
        for (int i = 0; i < 64; i++)
            if (mw[i] > 1u) { ok = 0; break; }
        is_i32_sh = ok;
    }
    __syncthreads();
    int is_i32 = is_i32_sh;
    const int* mi32 = (const int*)maskp;
    const unsigned char* mu8 = (const unsigned char*)maskp;

    const float* s0 = sc2 + (size_t)b * TT + tc * 512;
    const float* s1 = sc2 + (size_t)BB * TT + (size_t)b * TT + tc * 512;
    float local = 0.f;
    for (int t = tid; t < 512; t += 256) {
        size_t idx = (size_t)b * TT + tc * 512 + t;
        bool mv = is_i32 ? (mi32[idx] != 0) : (mu8[idx] != 0);
        float p = mv ? __expf(s0[t] + s1[t]) : 0.f;
        ws[t] = p;
        local += p;
    }
    __syncthreads();

    if (blockIdx.x == 0) {
        // write unnormalized p and the chunk sum
        for (int t = tid; t < 512; t += 256) w[(size_t)b * TT + tc * 512 + t] = ws[t];
#pragma unroll
        for (int o = 16; o; o >>= 1) local += __shfl_xor_sync(~0u, local, o);
        if ((tid & 31) == 0) red[tid >> 5] = local;
        __syncthreads();
        if (tid == 0) {
            float s = 0.f;
#pragma unroll
            for (int i = 0; i < 8; i++) s += red[i];
            psum[tc * BB + b] = s;
        }
    }

    const float* base = henc + (size_t)b * TT * DE + (size_t)tc * 512 * DE + e;
    float acc = 0.f;
#pragma unroll 8
    for (int t = 0; t < 512; t++) acc = fmaf(ws[t], base[(size_t)t * DE], acc);
    part[((size_t)tc * BB + b) * DE + e] = acc;
}

// ---------------- kernel 5: finalize — normalize ctx and w ----------------
__global__ void finalize_kernel(const float* __restrict__ part, const float* __restrict__ psum,
                                float* __restrict__ ctx, float* __restrict__ w) {
    int b = blockIdx.x;
    int tid = threadIdx.x;  // 512
    __shared__ float invS;
    if (tid == 0) {
        float s = 0.f;
#pragma unroll
        for (int p = 0; p < 8; p++) s += psum[p * BB + b];
        invS = 1.f / s;
    }
    __syncthreads();
    float inv = invS;
    {   // ctx: 512 e-columns, one per thread
        float s = 0.f;
#pragma unroll
        for (int p = 0; p < 8; p++) s += part[((size_t)p * BB + b) * DE + tid];
        ctx[(size_t)b * DE + tid] = s * inv;
    }
    for (int t = tid; t < TT; t += 512)
        w[(size_t)b * TT + t] *= inv;
}

// ---------------- host launcher ----------------
extern "C" void kernel_launch(void* const* d_in, const int* in_sizes, int n_in,
                              void* d_out, int out_size) {
    const float* h_enc = (const float*)d_in[0];
    const float* h_dec = (const float*)d_in[1];
    const float* Wq_w  = (const float*)d_in[2];
    const float* Wq_b  = (const float*)d_in[3];
    const float* Wk_w  = (const float*)d_in[4];
    const float* Wk_b  = (const float*)d_in[5];
    const float* v_w   = (const float*)d_in[6];
    const void*  mask  = (const void*)d_in[7];

    float* out = (float*)d_out;
    float* ctx = out;                 // [B, 512]
    float* w   = out + BB * DE;       // [B, 4096]

    void *p_wk, *p_qpk, *p_sc2, *p_part, *p_psum;
    cudaGetSymbolAddress(&p_wk, g_wk_bf);
    cudaGetSymbolAddress(&p_qpk, g_qpk);
    cudaGetSymbolAddress(&p_sc2, g_scores2);
    cudaGetSymbolAddress(&p_part, g_ctx_part);
    cudaGetSymbolAddress(&p_psum, g_psum);

    cudaFuncSetAttribute(gemm_score_kernel, cudaFuncAttributeMaxDynamicSharedMemorySize, GEMM_SMEM);

    convert_kernel<<<(DA * DE / 4) / 256, 256>>>(Wk_w, (__nv_bfloat16*)p_wk, DA * DE / 4);
    qpk_kernel<<<BB, 256>>>(h_dec, Wq_w, Wq_b, Wk_b, (float*)p_qpk);
    gemm_score_kernel<<<BB * 32 * 2, 256, GEMM_SMEM>>>(
        h_enc, (const __nv_bfloat16*)p_wk,
        (const float*)p_qpk, v_w, (float*)p_sc2);
    ctx_part_kernel<<<dim3(2, BB, 8), 256>>>(h_enc, (const float*)p_sc2, mask,
                                             w, (float*)p_part, (float*)p_psum);
    finalize_kernel<<<BB, 512>>>((const float*)p_part, (const float*)p_psum, ctx, w);
}